// round 6
// baseline (speedup 1.0000x reference)
#include <cuda_runtime.h>
#include <math.h>

#define NN 1024
#define DIM 512
#define QKVD 1536
#define HEADS 8
#define HD 64
#define BM 64
#define NSPLIT 2
#define MPART (NN / NSPLIT)

#define QKV_MT 128
#define QKV_NT 64
#define QKV_BLOCKS ((NN / QKV_MT) * (QKVD / QKV_NT))   // 192
#define LOC_BLOCKS (NN * NN / 256)                      // 4096

// Scratch (static device allocation only).
__device__ float g_qkv[NN * QKVD];
__device__ float g_S[(size_t)HEADS * NN * NN];
__device__ float g_Op[NSPLIT][HEADS][NN][HD];
__device__ float g_mx[NSPLIT][HEADS][NN];
__device__ float g_ls[NSPLIT][HEADS][NN];

// ---------------------------------------------------------------------------
// tf32 helpers
// ---------------------------------------------------------------------------
__device__ __forceinline__ unsigned cvt_tf32(float f) {
    unsigned u;
    asm("cvt.rna.tf32.f32 %0, %1;" : "=r"(u) : "f"(f));
    return u;
}
__device__ __forceinline__ void split_tf32(float f, unsigned& hi, unsigned& lo) {
    hi = cvt_tf32(f);
    lo = cvt_tf32(f - __uint_as_float(hi));
}
__device__ __forceinline__ void mma_tf32(float* c, const unsigned* a, const unsigned* b) {
    asm volatile(
        "mma.sync.aligned.m16n8k8.row.col.f32.tf32.tf32.f32 "
        "{%0,%1,%2,%3}, {%4,%5,%6,%7}, {%8,%9}, {%0,%1,%2,%3};"
        : "+f"(c[0]), "+f"(c[1]), "+f"(c[2]), "+f"(c[3])
        : "r"(a[0]), "r"(a[1]), "r"(a[2]), "r"(a[3]), "r"(b[0]), "r"(b[1]));
}

// ---------------------------------------------------------------------------
// K1 (combined): tf32 QKV GEMM blocks + location-bias blocks (as R5).
// ---------------------------------------------------------------------------
struct SmemQkv {
    float As[QKV_MT][20];
    float Bs[QKV_NT][20];
};
struct SmemLoc {
    float sW[8][64];
    float sb[8];
};

__global__ void __launch_bounds__(256) fused_pre(const float* __restrict__ x,
                                                 const float* __restrict__ W,
                                                 const float* __restrict__ locs,
                                                 const float* __restrict__ Wl,
                                                 const float* __restrict__ bl) {
    __shared__ char smem_raw[sizeof(SmemQkv)];
    const int t = threadIdx.x;

    if (blockIdx.x < QKV_BLOCKS) {
        SmemQkv* s = (SmemQkv*)smem_raw;
        const int qb = blockIdx.x;
        const int bm = (qb % (NN / QKV_MT)) * QKV_MT;
        const int bn = (qb / (NN / QKV_MT)) * QKV_NT;
        const int w  = t >> 5, l = t & 31;
        const int wm = (w & 3) * 32;
        const int wn = (w >> 2) * 32;
        const int lq = l >> 2, lr = l & 3;

        const int arow = t >> 1;
        const int akc  = (t & 1) * 8;
        const float* Ap = x + (size_t)(bm + arow) * DIM + akc;
        const float* Bp = W + (size_t)(bn + (arow & 63)) * DIM + akc;

        float4 ra0 = *(const float4*)Ap;
        float4 ra1 = *(const float4*)(Ap + 4);
        float4 rb0 = make_float4(0, 0, 0, 0), rb1 = rb0;
        if (t < 128) { rb0 = *(const float4*)Bp; rb1 = *(const float4*)(Bp + 4); }

        float acc[2][4][4] = {};

        for (int kk = 0; kk < DIM; kk += 16) {
            __syncthreads();
            *(float4*)&s->As[arow][akc]     = ra0;
            *(float4*)&s->As[arow][akc + 4] = ra1;
            if (t < 128) {
                *(float4*)&s->Bs[arow & 63][akc]     = rb0;
                *(float4*)&s->Bs[arow & 63][akc + 4] = rb1;
            }
            __syncthreads();
            if (kk + 16 < DIM) {
                ra0 = *(const float4*)(Ap + kk + 16);
                ra1 = *(const float4*)(Ap + kk + 20);
                if (t < 128) {
                    rb0 = *(const float4*)(Bp + kk + 16);
                    rb1 = *(const float4*)(Bp + kk + 20);
                }
            }
#pragma unroll
            for (int ks = 0; ks < 16; ks += 8) {
                unsigned ahi[2][4], alo[2][4];
#pragma unroll
                for (int mi = 0; mi < 2; mi++) {
                    const int r = wm + mi * 16;
                    split_tf32(s->As[r + lq][ks + lr],          ahi[mi][0], alo[mi][0]);
                    split_tf32(s->As[r + lq + 8][ks + lr],      ahi[mi][1], alo[mi][1]);
                    split_tf32(s->As[r + lq][ks + lr + 4],      ahi[mi][2], alo[mi][2]);
                    split_tf32(s->As[r + lq + 8][ks + lr + 4],  ahi[mi][3], alo[mi][3]);
                }
#pragma unroll
                for (int ni = 0; ni < 4; ni++) {
                    unsigned bhi[2], blo[2];
                    const int c = wn + ni * 8 + lq;
                    split_tf32(s->Bs[c][ks + lr],     bhi[0], blo[0]);
                    split_tf32(s->Bs[c][ks + lr + 4], bhi[1], blo[1]);
#pragma unroll
                    for (int mi = 0; mi < 2; mi++) {
                        mma_tf32(acc[mi][ni], ahi[mi], bhi);
                        mma_tf32(acc[mi][ni], ahi[mi], blo);
                        mma_tf32(acc[mi][ni], alo[mi], bhi);
                    }
                }
            }
        }
#pragma unroll
        for (int mi = 0; mi < 2; mi++)
#pragma unroll
            for (int ni = 0; ni < 4; ni++) {
                const int r = bm + wm + mi * 16 + lq;
                const int c = bn + wn + ni * 8 + lr * 2;
                *(float2*)&g_qkv[(size_t)r * QKVD + c] =
                    make_float2(acc[mi][ni][0], acc[mi][ni][1]);
                *(float2*)&g_qkv[(size_t)(r + 8) * QKVD + c] =
                    make_float2(acc[mi][ni][2], acc[mi][ni][3]);
            }
    } else {
        SmemLoc* s = (SmemLoc*)smem_raw;
        for (int i = t; i < 512; i += 256) s->sW[i >> 6][i & 63] = Wl[i];
        if (t < 8) s->sb[t] = bl[t];
        __syncthreads();

        const int lid = blockIdx.x - QKV_BLOCKS;
        const int n = lid >> 2;
        const int m = (lid & 3) * 256 + t;

        const float4 bn = ((const float4*)locs)[n];
        const float4 bm = ((const float4*)locs)[m];
        const float wn = bn.z - bn.x + 1.0f, hn = bn.w - bn.y + 1.0f;
        const float wm = bm.z - bm.x + 1.0f, hm = bm.w - bm.y + 1.0f;
        const float cxn = 0.5f * (bn.x + bn.z), cyn = 0.5f * (bn.y + bn.w);
        const float cxm = 0.5f * (bm.x + bm.z), cym = 0.5f * (bm.y + bm.w);

        float pos[4];
        pos[0] = __logf(fmaxf(fabsf((cxn - cxm) / wn), 1e-3f));
        pos[1] = __logf(fmaxf(fabsf((cyn - cym) / hn), 1e-3f));
        pos[2] = __logf(wm / wn);
        pos[3] = __logf(hm / hn);

        const float invd[8] = {100.0f, 42.1696503f, 17.7827941f, 7.49894209f,
                               3.16227766f, 1.33352143f, 0.562341325f, 0.237137371f};

        float acc[8];
#pragma unroll
        for (int h = 0; h < 8; h++) acc[h] = s->sb[h];

#pragma unroll
        for (int g = 0; g < 4; g++) {
#pragma unroll
            for (int j = 0; j < 8; j++) {
                float sn, cs;
                __sincosf(pos[g] * invd[j], &sn, &cs);
#pragma unroll
                for (int h = 0; h < 8; h++)
                    acc[h] = fmaf(sn, s->sW[h][g * 16 + j],
                                  fmaf(cs, s->sW[h][g * 16 + 8 + j], acc[h]));
            }
        }
        const size_t base = (size_t)n * NN + m;
#pragma unroll
        for (int h = 0; h < 8; h++)
            g_S[(size_t)h * NN * NN + base] = __logf(fmaxf(acc[h], 0.0f) + 1e-6f);
    }
}

// ---------------------------------------------------------------------------
// K2: split-KV flash attention on tensor cores (3-pass tf32).
// 8 warps = 4(m) x 2(n); warp tile 16x32 of the 64x64 S tile.
// Dynamic smem layout (floats):
//   QH[64*68] QL[64*68] KH[64*68] KL[64*68] VH[64*72] VL[64*72] pmax[2*64] psum[2*64]
// P (hi/lo) reuses the K buffers after S phase.
// ---------------------------------------------------------------------------
#define SQ 68
#define SV 72
#define OFF_QH 0
#define OFF_QL (64 * SQ)
#define OFF_KH (2 * 64 * SQ)
#define OFF_KL (3 * 64 * SQ)
#define OFF_VH (4 * 64 * SQ)
#define OFF_VL (4 * 64 * SQ + 64 * SV)
#define OFF_PM (4 * 64 * SQ + 2 * 64 * SV)
#define OFF_PS (OFF_PM + 2 * 64)
#define SMEM_FLOATS (OFF_PS + 2 * 64)

__global__ void __launch_bounds__(256, 2) fused_attn() {
    extern __shared__ float smem[];
    unsigned* sQh = (unsigned*)(smem + OFF_QH);
    unsigned* sQl = (unsigned*)(smem + OFF_QL);
    unsigned* sKh = (unsigned*)(smem + OFF_KH);
    unsigned* sKl = (unsigned*)(smem + OFF_KL);
    unsigned* sVh = (unsigned*)(smem + OFF_VH);
    unsigned* sVl = (unsigned*)(smem + OFF_VL);
    float* pmax = smem + OFF_PM;
    float* psum = smem + OFF_PS;

    const int t = threadIdx.x;
    const int w = t >> 5, l = t & 31;
    const int lq = l >> 2, lr = l & 3;
    const int mrow = (w & 3) * 16;     // warp q-row base
    const int wn2  = w >> 2;           // warp n half (0|1)
    const int ncol = wn2 * 32;         // warp key/d col base

    const int h   = blockIdx.x & 7;
    const int qt  = (blockIdx.x >> 3) & 15;
    const int sp  = blockIdx.x >> 7;
    const int bm  = qt * BM;
    const int m0g = sp * MPART;

    const float* Qg = g_qkv + h * HD;
    const float* Kg = g_qkv + DIM + h * HD;
    const float* Vg = g_qkv + 2 * DIM + h * HD;
    const float* Bg = g_S + (size_t)h * NN * NN;

    // Load + split Q tile [64][64]
    {
        const int qr = t >> 2;
        const int c0 = (t & 3) * 16;
        const float* Qp = Qg + (size_t)(bm + qr) * QKVD;
#pragma unroll
        for (int p = 0; p < 4; p++) {
            float4 v = *(const float4*)(Qp + c0 + p * 4);
            unsigned h0, l0, h1, l1, h2, l2, h3, l3;
            split_tf32(v.x, h0, l0); split_tf32(v.y, h1, l1);
            split_tf32(v.z, h2, l2); split_tf32(v.w, h3, l3);
            const int a = qr * SQ + c0 + p * 4;
            sQh[a] = h0; sQh[a + 1] = h1; sQh[a + 2] = h2; sQh[a + 3] = h3;
            sQl[a] = l0; sQl[a + 1] = l1; sQl[a + 2] = l2; sQl[a + 3] = l3;
        }
    }

    float o[4][4] = {};
    float rmax0 = -INFINITY, rmax1 = -INFINITY;
    float rsum0 = 0.0f, rsum1 = 0.0f;

    for (int mt = 0; mt < MPART / 64; mt++) {
        const int mbase = m0g + mt * 64;
        __syncthreads();  // prev iter's K(P)/V consumed

        // Load + split K, V tiles
        {
            const int rr = t >> 2;
            const int c0 = (t & 3) * 16;
            const float* Kp = Kg + (size_t)(mbase + rr) * QKVD;
            const float* Vp = Vg + (size_t)(mbase + rr) * QKVD;
#pragma unroll
            for (int p = 0; p < 4; p++) {
                float4 kv = *(const float4*)(Kp + c0 + p * 4);
                float4 vv = *(const float4*)(Vp + c0 + p * 4);
                unsigned h0, l0, h1, l1, h2, l2, h3, l3;
                split_tf32(kv.x, h0, l0); split_tf32(kv.y, h1, l1);
                split_tf32(kv.z, h2, l2); split_tf32(kv.w, h3, l3);
                int a = rr * SQ + c0 + p * 4;
                sKh[a] = h0; sKh[a + 1] = h1; sKh[a + 2] = h2; sKh[a + 3] = h3;
                sKl[a] = l0; sKl[a + 1] = l1; sKl[a + 2] = l2; sKl[a + 3] = l3;
                split_tf32(vv.x, h0, l0); split_tf32(vv.y, h1, l1);
                split_tf32(vv.z, h2, l2); split_tf32(vv.w, h3, l3);
                a = rr * SV + c0 + p * 4;
                sVh[a] = h0; sVh[a + 1] = h1; sVh[a + 2] = h2; sVh[a + 3] = h3;
                sVl[a] = l0; sVl[a + 1] = l1; sVl[a + 2] = l2; sVl[a + 3] = l3;
            }
        }
        __syncthreads();

        // ---- S = Q K^T (3-pass tf32) ----
        float sc[4][4] = {};
#pragma unroll
        for (int ks = 0; ks < 64; ks += 8) {
            unsigned ah[4], al_[4];
            const int ab = (mrow + lq) * SQ + ks + lr;
            ah[0] = sQh[ab];            ah[1] = sQh[ab + 8 * SQ];
            ah[2] = sQh[ab + 4];        ah[3] = sQh[ab + 8 * SQ + 4];
            al_[0] = sQl[ab];           al_[1] = sQl[ab + 8 * SQ];
            al_[2] = sQl[ab + 4];       al_[3] = sQl[ab + 8 * SQ + 4];
#pragma unroll
            for (int ni = 0; ni < 4; ni++) {
                const int bb = (ncol + ni * 8 + lq) * SQ + ks + lr;
                unsigned bh[2] = {sKh[bb], sKh[bb + 4]};
                unsigned bl[2] = {sKl[bb], sKl[bb + 4]};
                mma_tf32(sc[ni], ah, bh);
                mma_tf32(sc[ni], ah, bl);
                mma_tf32(sc[ni], al_, bh);
            }
        }

        // ---- bias + softmax ----
        float sv[4][4];
#pragma unroll
        for (int ni = 0; ni < 4; ni++) {
            const size_t cb = (size_t)(bm + mrow + lq) * NN + mbase + ncol + ni * 8 + lr * 2;
            float2 b0 = *(const float2*)(Bg + cb);
            float2 b1 = *(const float2*)(Bg + cb + 8 * NN);
            sv[ni][0] = fmaf(0.125f, sc[ni][0], b0.x);
            sv[ni][1] = fmaf(0.125f, sc[ni][1], b0.y);
            sv[ni][2] = fmaf(0.125f, sc[ni][2], b1.x);
            sv[ni][3] = fmaf(0.125f, sc[ni][3], b1.y);
        }
        float mx0 = fmaxf(fmaxf(sv[0][0], sv[0][1]), fmaxf(sv[1][0], sv[1][1]));
        mx0 = fmaxf(mx0, fmaxf(fmaxf(sv[2][0], sv[2][1]), fmaxf(sv[3][0], sv[3][1])));
        float mx1 = fmaxf(fmaxf(sv[0][2], sv[0][3]), fmaxf(sv[1][2], sv[1][3]));
        mx1 = fmaxf(mx1, fmaxf(fmaxf(sv[2][2], sv[2][3]), fmaxf(sv[3][2], sv[3][3])));
#pragma unroll
        for (int off = 1; off <= 2; off <<= 1) {
            mx0 = fmaxf(mx0, __shfl_xor_sync(0xffffffffu, mx0, off));
            mx1 = fmaxf(mx1, __shfl_xor_sync(0xffffffffu, mx1, off));
        }
        if (lr == 0) {
            pmax[wn2 * 64 + mrow + lq] = mx0;
            pmax[wn2 * 64 + mrow + lq + 8] = mx1;
        }
        __syncthreads();
        const float nm0 = fmaxf(rmax0, fmaxf(pmax[mrow + lq], pmax[64 + mrow + lq]));
        const float nm1 = fmaxf(rmax1, fmaxf(pmax[mrow + lq + 8], pmax[64 + mrow + lq + 8]));
        const float alf0 = __expf(rmax0 - nm0);
        const float alf1 = __expf(rmax1 - nm1);
        rmax0 = nm0; rmax1 = nm1;

        float pv[4][4];
        float ls0 = 0.0f, ls1 = 0.0f;
#pragma unroll
        for (int ni = 0; ni < 4; ni++) {
            pv[ni][0] = __expf(sv[ni][0] - nm0);
            pv[ni][1] = __expf(sv[ni][1] - nm0);
            pv[ni][2] = __expf(sv[ni][2] - nm1);
            pv[ni][3] = __expf(sv[ni][3] - nm1);
            ls0 += pv[ni][0] + pv[ni][1];
            ls1 += pv[ni][2] + pv[ni][3];
        }
#pragma unroll
        for (int off = 1; off <= 2; off <<= 1) {
            ls0 += __shfl_xor_sync(0xffffffffu, ls0, off);
            ls1 += __shfl_xor_sync(0xffffffffu, ls1, off);
        }
        if (lr == 0) {
            psum[wn2 * 64 + mrow + lq] = ls0;
            psum[wn2 * 64 + mrow + lq + 8] = ls1;
        }
        // write P hi/lo into the K buffers (all K reads finished before sync above)
#pragma unroll
        for (int ni = 0; ni < 4; ni++) {
            unsigned h0, l0, h1, l1;
            split_tf32(pv[ni][0], h0, l0); split_tf32(pv[ni][1], h1, l1);
            const int a0 = (mrow + lq) * SQ + ncol + ni * 8 + lr * 2;
            sKh[a0] = h0; sKh[a0 + 1] = h1; sKl[a0] = l0; sKl[a0 + 1] = l1;
            split_tf32(pv[ni][2], h0, l0); split_tf32(pv[ni][3], h1, l1);
            const int a1 = (mrow + lq + 8) * SQ + ncol + ni * 8 + lr * 2;
            sKh[a1] = h0; sKh[a1 + 1] = h1; sKl[a1] = l0; sKl[a1 + 1] = l1;
        }
        __syncthreads();
        rsum0 = rsum0 * alf0 + psum[mrow + lq] + psum[64 + mrow + lq];
        rsum1 = rsum1 * alf1 + psum[mrow + lq + 8] + psum[64 + mrow + lq + 8];
#pragma unroll
        for (int ni = 0; ni < 4; ni++) {
            o[ni][0] *= alf0; o[ni][1] *= alf0;
            o[ni][2] *= alf1; o[ni][3] *= alf1;
        }

        // ---- O += P V (3-pass tf32) ----
#pragma unroll
        for (int ks = 0; ks < 64; ks += 8) {
            unsigned ph[4], pl[4];
            const int pb = (mrow + lq) * SQ + ks + lr;
            ph[0] = sKh[pb];           ph[1] = sKh[pb + 8 * SQ];
            ph[2] = sKh[pb + 4];       ph[3] = sKh[pb + 8 * SQ + 4];
            pl[0] = sKl[pb];           pl[1] = sKl[pb + 8 * SQ];
            pl[2] = sKl[pb + 4];       pl[3] = sKl[pb + 8 * SQ + 4];
#pragma unroll
            for (int ni = 0; ni < 4; ni++) {
                const int vb = (ks + lr) * SV + ncol + ni * 8 + lq;
                unsigned bh[2] = {sVh[vb], sVh[vb + 4 * SV]};
                unsigned bl[2] = {sVl[vb], sVl[vb + 4 * SV]};
                mma_tf32(o[ni], ph, bh);
                mma_tf32(o[ni], ph, bl);
                mma_tf32(o[ni], pl, bh);
            }
        }
    }

    // ---- write partials ----
    const float inv0 = 1.0f;  // keep unnormalized; merge_k normalizes
#pragma unroll
    for (int ni = 0; ni < 4; ni++) {
        const int d = ncol + ni * 8 + lr * 2;
        *(float2*)&g_Op[sp][h][bm + mrow + lq][d] = make_float2(o[ni][0] * inv0, o[ni][1] * inv0);
        *(float2*)&g_Op[sp][h][bm + mrow + lq + 8][d] = make_float2(o[ni][2] * inv0, o[ni][3] * inv0);
    }
    if (lr == 0 && wn2 == 0) {
        g_mx[sp][h][bm + mrow + lq] = rmax0;
        g_ls[sp][h][bm + mrow + lq] = rsum0;
        g_mx[sp][h][bm + mrow + lq + 8] = rmax1;
        g_ls[sp][h][bm + mrow + lq + 8] = rsum1;
    }
}

// ---------------------------------------------------------------------------
// K3: merge split partials.
// ---------------------------------------------------------------------------
__global__ void __launch_bounds__(256) merge_k(float* __restrict__ out) {
    const int w = (blockIdx.x * 8) + (threadIdx.x >> 5);
    const int lane = threadIdx.x & 31;
    const int h = w >> 10;
    const int n = w & 1023;

    const float m0 = g_mx[0][h][n], m1 = g_mx[1][h][n];
    const float mM = fmaxf(m0, m1);
    const float e0 = __expf(m0 - mM), e1 = __expf(m1 - mM);
    const float inv = 1.0f / (g_ls[0][h][n] * e0 + g_ls[1][h][n] * e1);

    const float2 o0 = *(const float2*)&g_Op[0][h][n][lane * 2];
    const float2 o1 = *(const float2*)&g_Op[1][h][n][lane * 2];
    float2 r;
    r.x = (o0.x * e0 + o1.x * e1) * inv;
    r.y = (o0.y * e0 + o1.y * e1) * inv;
    *(float2*)(out + (size_t)n * DIM + h * HD + lane * 2) = r;
}

// ---------------------------------------------------------------------------
extern "C" void kernel_launch(void* const* d_in, const int* in_sizes, int n_in,
                              void* d_out, int out_size) {
    const float* x    = (const float*)d_in[0];
    const float* locs = (const float*)d_in[2];
    const float* Wqkv = (const float*)d_in[3];
    const float* Wloc = (const float*)d_in[4];
    const float* bloc = (const float*)d_in[5];
    float* out = (float*)d_out;

    cudaFuncSetAttribute(fused_attn, cudaFuncAttributeMaxDynamicSharedMemorySize,
                         SMEM_FLOATS * 4);

    fused_pre<<<QKV_BLOCKS + LOC_BLOCKS, 256>>>(x, Wqkv, locs, Wloc, bloc);
    fused_attn<<<(NN / BM) * HEADS * NSPLIT, 256, SMEM_FLOATS * 4>>>();
    merge_k<<<HEADS * NN / 8, 256>>>(out);
}

// round 8
// speedup vs baseline: 1.0254x; 1.0254x over previous
#include <cuda_runtime.h>
#include <cuda_bf16.h>
#include <math.h>

#define NN 1024
#define DIM 512
#define QKVD 1536
#define HEADS 8
#define HD 64
#define BM 64
#define NSPLIT 2
#define MPART (NN / NSPLIT)

#define QKV_MT 128
#define QKV_NT 64
#define QKV_BLOCKS ((NN / QKV_MT) * (QKVD / QKV_NT))   // 192

// Scratch (static device allocation only).
__device__ float g_qkv[NN * QKVD];
__device__ float g_S[(size_t)HEADS * NN * NN];
__device__ float g_Op[NSPLIT][HEADS][NN][HD];
__device__ float g_mx[NSPLIT][HEADS][NN];
__device__ float g_ls[NSPLIT][HEADS][NN];

// ---------------------------------------------------------------------------
// helpers
// ---------------------------------------------------------------------------
__device__ __forceinline__ unsigned cvt_tf32(float f) {
    unsigned u;
    asm("cvt.rna.tf32.f32 %0, %1;" : "=r"(u) : "f"(f));
    return u;
}
__device__ __forceinline__ void split_tf32(float f, unsigned& hi, unsigned& lo) {
    hi = cvt_tf32(f);
    lo = cvt_tf32(f - __uint_as_float(hi));
}
__device__ __forceinline__ void mma_tf32(float* c, const unsigned* a, const unsigned* b) {
    asm volatile(
        "mma.sync.aligned.m16n8k8.row.col.f32.tf32.tf32.f32 "
        "{%0,%1,%2,%3}, {%4,%5,%6,%7}, {%8,%9}, {%0,%1,%2,%3};"
        : "+f"(c[0]), "+f"(c[1]), "+f"(c[2]), "+f"(c[3])
        : "r"(a[0]), "r"(a[1]), "r"(a[2]), "r"(a[3]), "r"(b[0]), "r"(b[1]));
}
__device__ __forceinline__ void mma_bf16(float* c, const unsigned* a, const unsigned* b) {
    asm volatile(
        "mma.sync.aligned.m16n8k16.row.col.f32.bf16.bf16.f32 "
        "{%0,%1,%2,%3}, {%4,%5,%6,%7}, {%8,%9}, {%0,%1,%2,%3};"
        : "+f"(c[0]), "+f"(c[1]), "+f"(c[2]), "+f"(c[3])
        : "r"(a[0]), "r"(a[1]), "r"(a[2]), "r"(a[3]), "r"(b[0]), "r"(b[1]));
}
// pack two floats to bf16x2: lower half = first arg (even k), upper = second
__device__ __forceinline__ unsigned bfpack(float lo_e, float hi_e) {
    unsigned r;
    asm("cvt.rn.bf16x2.f32 %0, %1, %2;" : "=r"(r) : "f"(hi_e), "f"(lo_e));
    return r;
}
__device__ __forceinline__ float bfres(float f) {
    return f - __bfloat162float(__float2bfloat16(f));
}

// ---------------------------------------------------------------------------
// K1: tf32 QKV GEMM. 128x64 tile, 8 warps (4m x 2n).
// ---------------------------------------------------------------------------
__global__ void __launch_bounds__(256) qkv_gemm(const float* __restrict__ x,
                                                const float* __restrict__ W) {
    __shared__ float As[QKV_MT][20];
    __shared__ float Bs[QKV_NT][20];
    const int t = threadIdx.x;
    const int qb = blockIdx.x;
    const int bm = (qb % (NN / QKV_MT)) * QKV_MT;
    const int bn = (qb / (NN / QKV_MT)) * QKV_NT;
    const int w  = t >> 5, l = t & 31;
    const int wm = (w & 3) * 32;
    const int wn = (w >> 2) * 32;
    const int lq = l >> 2, lr = l & 3;

    const int arow = t >> 1;
    const int akc  = (t & 1) * 8;
    const float* Ap = x + (size_t)(bm + arow) * DIM + akc;
    const float* Bp = W + (size_t)(bn + (arow & 63)) * DIM + akc;

    float4 ra0 = *(const float4*)Ap;
    float4 ra1 = *(const float4*)(Ap + 4);
    float4 rb0 = make_float4(0, 0, 0, 0), rb1 = rb0;
    if (t < 128) { rb0 = *(const float4*)Bp; rb1 = *(const float4*)(Bp + 4); }

    float acc[2][4][4] = {};

    for (int kk = 0; kk < DIM; kk += 16) {
        __syncthreads();
        *(float4*)&As[arow][akc]     = ra0;
        *(float4*)&As[arow][akc + 4] = ra1;
        if (t < 128) {
            *(float4*)&Bs[arow & 63][akc]     = rb0;
            *(float4*)&Bs[arow & 63][akc + 4] = rb1;
        }
        __syncthreads();
        if (kk + 16 < DIM) {
            ra0 = *(const float4*)(Ap + kk + 16);
            ra1 = *(const float4*)(Ap + kk + 20);
            if (t < 128) {
                rb0 = *(const float4*)(Bp + kk + 16);
                rb1 = *(const float4*)(Bp + kk + 20);
            }
        }
#pragma unroll
        for (int ks = 0; ks < 16; ks += 8) {
            unsigned ahi[2][4], alo[2][4];
#pragma unroll
            for (int mi = 0; mi < 2; mi++) {
                const int r = wm + mi * 16;
                split_tf32(As[r + lq][ks + lr],          ahi[mi][0], alo[mi][0]);
                split_tf32(As[r + lq + 8][ks + lr],      ahi[mi][1], alo[mi][1]);
                split_tf32(As[r + lq][ks + lr + 4],      ahi[mi][2], alo[mi][2]);
                split_tf32(As[r + lq + 8][ks + lr + 4],  ahi[mi][3], alo[mi][3]);
            }
#pragma unroll
            for (int ni = 0; ni < 4; ni++) {
                unsigned bhi[2], blo[2];
                const int c = wn + ni * 8 + lq;
                split_tf32(Bs[c][ks + lr],     bhi[0], blo[0]);
                split_tf32(Bs[c][ks + lr + 4], bhi[1], blo[1]);
#pragma unroll
                for (int mi = 0; mi < 2; mi++) {
                    mma_tf32(acc[mi][ni], ahi[mi], bhi);
                    mma_tf32(acc[mi][ni], ahi[mi], blo);
                    mma_tf32(acc[mi][ni], alo[mi], bhi);
                }
            }
        }
    }
#pragma unroll
    for (int mi = 0; mi < 2; mi++)
#pragma unroll
        for (int ni = 0; ni < 4; ni++) {
            const int r = bm + wm + mi * 16 + lq;
            const int c = bn + wn + ni * 8 + lr * 2;
            *(float2*)&g_qkv[(size_t)r * QKVD + c] =
                make_float2(acc[mi][ni][0], acc[mi][ni][1]);
            *(float2*)&g_qkv[(size_t)(r + 8) * QKVD + c] =
                make_float2(acc[mi][ni][2], acc[mi][ni][3]);
        }
}

// ---------------------------------------------------------------------------
// K2: location bias (standalone, high occupancy).
// ---------------------------------------------------------------------------
__global__ void __launch_bounds__(256, 4) loc_bias(const float* __restrict__ locs,
                                                   const float* __restrict__ Wl,
                                                   const float* __restrict__ bl) {
    __shared__ float sW[8][64];
    __shared__ float sb[8];
    const int t = threadIdx.x;
    for (int i = t; i < 512; i += 256) sW[i >> 6][i & 63] = Wl[i];
    if (t < 8) sb[t] = bl[t];
    __syncthreads();

    const int lid = blockIdx.x;
    const int n = lid >> 2;
    const int m = (lid & 3) * 256 + t;

    const float4 bn = ((const float4*)locs)[n];
    const float4 bm = ((const float4*)locs)[m];
    const float wn = bn.z - bn.x + 1.0f, hn = bn.w - bn.y + 1.0f;
    const float wm = bm.z - bm.x + 1.0f, hm = bm.w - bm.y + 1.0f;
    const float cxn = 0.5f * (bn.x + bn.z), cyn = 0.5f * (bn.y + bn.w);
    const float cxm = 0.5f * (bm.x + bm.z), cym = 0.5f * (bm.y + bm.w);

    float pos[4];
    pos[0] = __logf(fmaxf(fabsf((cxn - cxm) / wn), 1e-3f));
    pos[1] = __logf(fmaxf(fabsf((cyn - cym) / hn), 1e-3f));
    pos[2] = __logf(wm / wn);
    pos[3] = __logf(hm / hn);

    const float invd[8] = {100.0f, 42.1696503f, 17.7827941f, 7.49894209f,
                           3.16227766f, 1.33352143f, 0.562341325f, 0.237137371f};

    float acc[8];
#pragma unroll
    for (int h = 0; h < 8; h++) acc[h] = sb[h];

#pragma unroll
    for (int g = 0; g < 4; g++) {
#pragma unroll
        for (int j = 0; j < 8; j++) {
            float sn, cs;
            __sincosf(pos[g] * invd[j], &sn, &cs);
#pragma unroll
            for (int h = 0; h < 8; h++)
                acc[h] = fmaf(sn, sW[h][g * 16 + j],
                              fmaf(cs, sW[h][g * 16 + 8 + j], acc[h]));
        }
    }
    const size_t base = (size_t)n * NN + m;
#pragma unroll
    for (int h = 0; h < 8; h++)
        g_S[(size_t)h * NN * NN + base] = __logf(fmaxf(acc[h], 0.0f) + 1e-6f);
}

// ---------------------------------------------------------------------------
// K3: split-KV flash attention, bf16x2 hi/lo 3-pass, mma m16n8k16.
// 8 warps = 4(m-rows of 16) x 2(n-halves of 32). smem stride 36 u32.
// ---------------------------------------------------------------------------
#define SQ2 36
#define A_Qh 0
#define A_Ql (64 * SQ2)
#define A_Kh (2 * 64 * SQ2)
#define A_Kl (3 * 64 * SQ2)
#define A_Vh (4 * 64 * SQ2)
#define A_Vl (5 * 64 * SQ2)
#define A_PM (6 * 64 * SQ2)
#define A_PS (A_PM + 128)
#define ATTN_SMEM_U32 (A_PS + 128)

// Load one 64-float row-segment (16 floats per thread, 4 threads/row) and
// store hi/lo bf16x2 at [row][pair].
__device__ __forceinline__ void load_split_row(const float* __restrict__ gp,
                                               unsigned* sh, unsigned* sl,
                                               int row, int quarter) {
    const float* p = gp + quarter * 16;
    float4 f0 = *(const float4*)p;
    float4 f1 = *(const float4*)(p + 4);
    float4 f2 = *(const float4*)(p + 8);
    float4 f3 = *(const float4*)(p + 12);
    const float f[16] = {f0.x, f0.y, f0.z, f0.w, f1.x, f1.y, f1.z, f1.w,
                         f2.x, f2.y, f2.z, f2.w, f3.x, f3.y, f3.z, f3.w};
    unsigned hi[8], lo[8];
#pragma unroll
    for (int j = 0; j < 8; j++) {
        hi[j] = bfpack(f[2 * j], f[2 * j + 1]);
        lo[j] = bfpack(bfres(f[2 * j]), bfres(f[2 * j + 1]));
    }
    const int a = row * SQ2 + quarter * 8;
    *(uint4*)&sh[a]     = make_uint4(hi[0], hi[1], hi[2], hi[3]);
    *(uint4*)&sh[a + 4] = make_uint4(hi[4], hi[5], hi[6], hi[7]);
    *(uint4*)&sl[a]     = make_uint4(lo[0], lo[1], lo[2], lo[3]);
    *(uint4*)&sl[a + 4] = make_uint4(lo[4], lo[5], lo[6], lo[7]);
}

__global__ void __launch_bounds__(256) fused_attn() {
    extern __shared__ unsigned sm[];
    unsigned* sQh = sm + A_Qh;
    unsigned* sQl = sm + A_Ql;
    unsigned* sKh = sm + A_Kh;   // K in S phase; P in PV phase
    unsigned* sKl = sm + A_Kl;
    unsigned* sVh = sm + A_Vh;   // transposed: [d][mpair]
    unsigned* sVl = sm + A_Vl;
    float* pmax = (float*)(sm + A_PM);
    float* psum = (float*)(sm + A_PS);

    const int t = threadIdx.x;
    const int w = t >> 5, l = t & 31;
    const int lq = l >> 2, lr = l & 3;
    const int mrow = (w & 3) * 16;
    const int wn2  = w >> 2;
    const int ncol = wn2 * 32;

    const int h   = blockIdx.x & 7;
    const int qt  = (blockIdx.x >> 3) & 15;
    const int sp  = blockIdx.x >> 7;
    const int bm  = qt * BM;
    const int m0g = sp * MPART;

    const float* Qg = g_qkv + h * HD;
    const float* Kg = g_qkv + DIM + h * HD;
    const float* Vg = g_qkv + 2 * DIM + h * HD;
    const float* Bg = g_S + (size_t)h * NN * NN;

    // ---- load + split Q [64][64] : 4 threads per row, 16 floats each ----
    {
        const int row = t >> 2;
        load_split_row(Qg + (size_t)(bm + row) * QKVD, sQh, sQl, row, t & 3);
    }

    float o[4][4] = {};
    float rmax0 = -INFINITY, rmax1 = -INFINITY;
    float rsum0 = 0.0f, rsum1 = 0.0f;

    for (int mt = 0; mt < MPART / 64; mt++) {
        const int mbase = m0g + mt * 64;
        __syncthreads();  // prev iter fully consumed (incl. P in sK*)

        // ---- load + split K [m][k] ----
        {
            const int row = t >> 2;
            load_split_row(Kg + (size_t)(mbase + row) * QKVD, sKh, sKl, row, t & 3);
        }
        // ---- load + split V, transposed to [d][mpair] ----
        {
            const int mp = t & 31;
            const int d0 = (t >> 5) * 8;
            const float* Vp0 = Vg + (size_t)(mbase + 2 * mp) * QKVD + d0;
            const float* Vp1 = Vp0 + QKVD;
            float4 a0 = *(const float4*)Vp0;
            float4 a1 = *(const float4*)(Vp0 + 4);
            float4 b0 = *(const float4*)Vp1;
            float4 b1 = *(const float4*)(Vp1 + 4);
            const float va[8] = {a0.x, a0.y, a0.z, a0.w, a1.x, a1.y, a1.z, a1.w};
            const float vb[8] = {b0.x, b0.y, b0.z, b0.w, b1.x, b1.y, b1.z, b1.w};
#pragma unroll
            for (int d = 0; d < 8; d++) {
                sVh[(d0 + d) * SQ2 + mp] = bfpack(va[d], vb[d]);
                sVl[(d0 + d) * SQ2 + mp] = bfpack(bfres(va[d]), bfres(vb[d]));
            }
        }
        // bias into regs (gmem, overlaps with smem fill)
        float2 bia0[4], bia1[4];
#pragma unroll
        for (int ni = 0; ni < 4; ni++) {
            const size_t cb = (size_t)(bm + mrow + lq) * NN + mbase + ncol + ni * 8 + lr * 2;
            bia0[ni] = *(const float2*)(Bg + cb);
            bia1[ni] = *(const float2*)(Bg + cb + 8 * NN);
        }
        __syncthreads();

        // ---- S = Q K^T ----
        float sc[4][4] = {};
#pragma unroll
        for (int s = 0; s < 4; s++) {
            const int ks2 = s * 8;
            unsigned ah[4], al_[4];
            const int ab = (mrow + lq) * SQ2 + ks2 + lr;
            ah[0] = sQh[ab];  ah[1] = sQh[ab + 8 * SQ2];
            ah[2] = sQh[ab + 4]; ah[3] = sQh[ab + 8 * SQ2 + 4];
            al_[0] = sQl[ab]; al_[1] = sQl[ab + 8 * SQ2];
            al_[2] = sQl[ab + 4]; al_[3] = sQl[ab + 8 * SQ2 + 4];
#pragma unroll
            for (int ni = 0; ni < 4; ni++) {
                const int bb = (ncol + ni * 8 + lq) * SQ2 + ks2 + lr;
                unsigned bh[2] = {sKh[bb], sKh[bb + 4]};
                unsigned bl[2] = {sKl[bb], sKl[bb + 4]};
                mma_bf16(sc[ni], ah, bh);
                mma_bf16(sc[ni], ah, bl);
                mma_bf16(sc[ni], al_, bh);
            }
        }

        // ---- bias + online softmax ----
        float sv[4][4];
#pragma unroll
        for (int ni = 0; ni < 4; ni++) {
            sv[ni][0] = fmaf(0.125f, sc[ni][0], bia0[ni].x);
            sv[ni][1] = fmaf(0.125f, sc[ni][1], bia0[ni].y);
            sv[ni][2] = fmaf(0.125f, sc[ni][2], bia1[ni].x);
            sv[ni][3] = fmaf(0.125f, sc[ni][3], bia1[ni].y);
        }
        float mx0 = fmaxf(fmaxf(sv[0][0], sv[0][1]), fmaxf(sv[1][0], sv[1][1]));
        mx0 = fmaxf(mx0, fmaxf(fmaxf(sv[2][0], sv[2][1]), fmaxf(sv[3][0], sv[3][1])));
        float mx1 = fmaxf(fmaxf(sv[0][2], sv[0][3]), fmaxf(sv[1][2], sv[1][3]));
        mx1 = fmaxf(mx1, fmaxf(fmaxf(sv[2][2], sv[2][3]), fmaxf(sv[3][2], sv[3][3])));
#pragma unroll
        for (int off = 1; off <= 2; off <<= 1) {
            mx0 = fmaxf(mx0, __shfl_xor_sync(0xffffffffu, mx0, off));
            mx1 = fmaxf(mx1, __shfl_xor_sync(0xffffffffu, mx1, off));
        }
        if (lr == 0) {
            pmax[wn2 * 64 + mrow + lq] = mx0;
            pmax[wn2 * 64 + mrow + lq + 8] = mx1;
        }
        __syncthreads();  // all K-mma reads done; pmax visible
        const float nm0 = fmaxf(rmax0, fmaxf(pmax[mrow + lq], pmax[64 + mrow + lq]));
        const float nm1 = fmaxf(rmax1, fmaxf(pmax[mrow + lq + 8], pmax[64 + mrow + lq + 8]));
        const float alf0 = __expf(rmax0 - nm0);
        const float alf1 = __expf(rmax1 - nm1);
        rmax0 = nm0; rmax1 = nm1;

        float pv[4][4];
        float ls0 = 0.0f, ls1 = 0.0f;
#pragma unroll
        for (int ni = 0; ni < 4; ni++) {
            pv[ni][0] = __expf(sv[ni][0] - nm0);
            pv[ni][1] = __expf(sv[ni][1] - nm0);
            pv[ni][2] = __expf(sv[ni][2] - nm1);
            pv[ni][3] = __expf(sv[ni][3] - nm1);
            ls0 += pv[ni][0] + pv[ni][1];
            ls1 += pv[ni][2] + pv[ni][3];
        }
#pragma unroll
        for (int off = 1; off <= 2; off <<= 1) {
            ls0 += __shfl_xor_sync(0xffffffffu, ls0, off);
            ls1 += __shfl_xor_sync(0xffffffffu, ls1, off);
        }
        if (lr == 0) {
            psum[wn2 * 64 + mrow + lq] = ls0;
            psum[wn2 * 64 + mrow + lq + 8] = ls1;
        }
        // ---- P (hi/lo bf16x2) into the K buffers ----
#pragma unroll
        for (int ni = 0; ni < 4; ni++) {
            const int c = ncol / 2 + ni * 4 + lr;
            const int a0 = (mrow + lq) * SQ2 + c;
            const int a1 = (mrow + lq + 8) * SQ2 + c;
            sKh[a0] = bfpack(pv[ni][0], pv[ni][1]);
            sKl[a0] = bfpack(bfres(pv[ni][0]), bfres(pv[ni][1]));
            sKh[a1] = bfpack(pv[ni][2], pv[ni][3]);
            sKl[a1] = bfpack(bfres(pv[ni][2]), bfres(pv[ni][3]));
        }
        __syncthreads();
        rsum0 = rsum0 * alf0 + psum[mrow + lq] + psum[64 + mrow + lq];
        rsum1 = rsum1 * alf1 + psum[mrow + lq + 8] + psum[64 + mrow + lq + 8];
#pragma unroll
        for (int ni = 0; ni < 4; ni++) {
            o[ni][0] *= alf0; o[ni][1] *= alf0;
            o[ni][2] *= alf1; o[ni][3] *= alf1;
        }

        // ---- O += P V ----
#pragma unroll
        for (int s = 0; s < 4; s++) {
            const int ks2 = s * 8;
            unsigned ph[4], pl[4];
            const int pb = (mrow + lq) * SQ2 + ks2 + lr;
            ph[0] = sKh[pb];  ph[1] = sKh[pb + 8 * SQ2];
            ph[2] = sKh[pb + 4]; ph[3] = sKh[pb + 8 * SQ2 + 4];
            pl[0] = sKl[pb];  pl[1] = sKl[pb + 8 * SQ2];
            pl[2] = sKl[pb + 4]; pl[3] = sKl[pb + 8 * SQ2 + 4];
#pragma unroll
            for (int ni = 0; ni < 4; ni++) {
                const int vb = (ncol + ni * 8 + lq) * SQ2 + ks2 + lr;
                unsigned bh[2] = {sVh[vb], sVh[vb + 4]};
                unsigned bl[2] = {sVl[vb], sVl[vb + 4]};
                mma_bf16(o[ni], ph, bh);
                mma_bf16(o[ni], ph, bl);
                mma_bf16(o[ni], pl, bh);
            }
        }
    }

    // ---- write partials ----
#pragma unroll
    for (int ni = 0; ni < 4; ni++) {
        const int d = ncol + ni * 8 + lr * 2;
        *(float2*)&g_Op[sp][h][bm + mrow + lq][d] = make_float2(o[ni][0], o[ni][1]);
        *(float2*)&g_Op[sp][h][bm + mrow + lq + 8][d] = make_float2(o[ni][2], o[ni][3]);
    }
    if (lr == 0 && wn2 == 0) {
        g_mx[sp][h][bm + mrow + lq] = rmax0;
        g_ls[sp][h][bm + mrow + lq] = rsum0;
        g_mx[sp][h][bm + mrow + lq + 8] = rmax1;
        g_ls[sp][h][bm + mrow + lq + 8] = rsum1;
    }
}

// ---------------------------------------------------------------------------
// K4: merge split partials.
// ---------------------------------------------------------------------------
__global__ void __launch_bounds__(256) merge_k(float* __restrict__ out) {
    const int w = (blockIdx.x * 8) + (threadIdx.x >> 5);
    const int lane = threadIdx.x & 31;
    const int h = w >> 10;
    const int n = w & 1023;

    const float m0 = g_mx[0][h][n], m1 = g_mx[1][h][n];
    const float mM = fmaxf(m0, m1);
    const float e0 = __expf(m0 - mM), e1 = __expf(m1 - mM);
    const float inv = 1.0f / (g_ls[0][h][n] * e0 + g_ls[1][h][n] * e1);

    const float2 o0 = *(const float2*)&g_Op[0][h][n][lane * 2];
    const float2 o1 = *(const float2*)&g_Op[1][h][n][lane * 2];
    float2 r;
    r.x = (o0.x * e0 + o1.x * e1) * inv;
    r.y = (o0.y * e0 + o1.y * e1) * inv;
    *(float2*)(out + (size_t)n * DIM + h * HD + lane * 2) = r;
}

// ---------------------------------------------------------------------------
extern "C" void kernel_launch(void* const* d_in, const int* in_sizes, int n_in,
                              void* d_out, int out_size) {
    const float* x    = (const float*)d_in[0];
    const float* locs = (const float*)d_in[2];
    const float* Wqkv = (const float*)d_in[3];
    const float* Wloc = (const float*)d_in[4];
    const float* bloc = (const float*)d_in[5];
    float* out = (float*)d_out;

    cudaFuncSetAttribute(fused_attn, cudaFuncAttributeMaxDynamicSharedMemorySize,
                         ATTN_SMEM_U32 * 4);

    qkv_gemm<<<QKV_BLOCKS, 256>>>(x, Wqkv);
    loc_bias<<<NN * NN / 256, 256>>>(locs, Wloc, bloc);
    fused_attn<<<(NN / BM) * HEADS * NSPLIT, 256, ATTN_SMEM_U32 * 4>>>();
    merge_k<<<HEADS * NN / 8, 256>>>(out);
}